// round 4
// baseline (speedup 1.0000x reference)
#include <cuda_runtime.h>
#include <cuda_bf16.h>

// ODE-GRU: B=128 sequences, L=2048 steps, I=D=64.
// One CTA per batch element (serial recurrence in h), 256 threads.
// All weights (512 rows x 64 floats) distributed into registers: 2 rows/thread.
// Smem carries only the broadcast vectors (h, t1, h_ode, x, gx, gh).
// 4 barriers/step; gx (input-gate GEMV, off the h-critical-path) runs in
// parallel with the diff-MLP first layer in phase P1.

#define NB 128
#define NL 2048
#define NI 64
#define ND 64
#define NG 192  // 3*D

__device__ __forceinline__ float dot64(const float* __restrict__ w,
                                       const float* __restrict__ v)
{
    const float4* __restrict__ v4 = (const float4*)v;
    float a0 = 0.f, a1 = 0.f, a2 = 0.f, a3 = 0.f;
#pragma unroll
    for (int q = 0; q < 16; q++) {
        float4 vv = v4[q];
        a0 = fmaf(w[4*q+0], vv.x, a0);
        a1 = fmaf(w[4*q+1], vv.y, a1);
        a2 = fmaf(w[4*q+2], vv.z, a2);
        a3 = fmaf(w[4*q+3], vv.w, a3);
    }
    return (a0 + a1) + (a2 + a3);
}

__device__ __forceinline__ float sigmoidf_(float a) {
    // abs error ~1e-7; no cancellation
    return 1.f / (1.f + __expf(-a));
}

__global__ __launch_bounds__(256, 1)
void odegru_kernel(const float* __restrict__ x,
                   const float* __restrict__ tdel,
                   const int*   __restrict__ seq,
                   const float* __restrict__ h0,
                   const float* __restrict__ w_ih,
                   const float* __restrict__ w_hh,
                   const float* __restrict__ b_ih,
                   const float* __restrict__ b_hh,
                   const float* __restrict__ dw1,
                   const float* __restrict__ db1,
                   const float* __restrict__ dw2,
                   const float* __restrict__ db2,
                   float* __restrict__ out)
{
    const int b   = blockIdx.x;
    const int tid = threadIdx.x;

    __shared__ __align__(16) float sh_h[ND];
    __shared__ __align__(16) float sh_t1[ND];
    __shared__ __align__(16) float sh_ho[ND];
    __shared__ __align__(16) float sh_gx[NG];
    __shared__ __align__(16) float sh_gh[NG];
    __shared__ __align__(16) float sh_x[2][NI];
    __shared__ float sh_dt[2];

    // ---- per-thread weight rows (stay in registers) ----
    // thr   0- 63: wX = dw1 row j        (P1)   wY = w_hh row 128+j (P3)
    // thr  64-127: wX = dw2 row j        (P2)   wY = w_ih row j     (P1)
    // thr 128-255: wX = w_hh row tid-128 (P3)   wY = w_ih row tid-64(P1)
    float wX[64], wY[64];
    float bX, bY;
    const float* pX;
    const float* pY;
    if (tid < 64) {
        pX = dw1 + tid * 64;          bX = db1[tid];
        pY = w_hh + (128 + tid) * 64; bY = b_hh[128 + tid];
    } else if (tid < 128) {
        int j = tid - 64;
        pX = dw2 + j * 64;            bX = db2[j];
        pY = w_ih + j * 64;           bY = b_ih[j];
    } else {
        int c = tid - 128;
        pX = w_hh + c * 64;           bX = b_hh[c];
        int c2 = tid - 64;
        pY = w_ih + c2 * 64;          bY = b_ih[c2];
    }
#pragma unroll
    for (int k = 0; k < 64; k++) { wX[k] = pX[k]; wY[k] = pY[k]; }

    const int sl = seq[b];
    const float* xb   = x + (size_t)b * NL * NI;
    float* outb       = out + (size_t)b * NL * ND;

    if (tid < 64) {
        sh_h[tid] = h0[tid];
        sh_x[0][tid] = xb[tid];            // t=0 always live (sl >= 1)
    }
    if (tid == 64) sh_dt[0] = tdel[(size_t)b * NL];

    float fin = 0.f;
    __syncthreads();

    for (int t = 0; t < NL; t++) {
        const int cur = t & 1, nxt = cur ^ 1;
        const int tn  = t + 1;

        // issue next-step prefetch early (consumed in P4)
        float xr = 0.f, dtr = 0.f;
        if (tn < NL) {
            if (tid < 64)   xr  = xb[(size_t)tn * NI + tid];
            if (tid == 64)  dtr = tdel[(size_t)b * NL + tn];
        }

        // ---- P1: u = tanh(h*dw1^T + db1)  ||  gx = x_t*w_ih^T + b_ih ----
        if (tid < 64) {
            float u = dot64(wX, sh_h);
            sh_t1[tid] = tanhf(u + bX);
        } else {
            float g = dot64(wY, sh_x[cur]);
            sh_gx[tid - 64] = g + bY;
        }
        __syncthreads();

        // ---- P2: d = u*dw2^T + db2;  h_ode = h + d*dt ----
        if (tid >= 64 && tid < 128) {
            int j = tid - 64;
            float d = dot64(wX, sh_t1);
            sh_ho[j] = fmaf(d + bX, sh_dt[cur], sh_h[j]);
        }
        __syncthreads();

        // ---- P3: gh = h_ode*w_hh^T + b_hh ----
        if (tid < 64) {
            float g = dot64(wY, sh_ho);
            sh_gh[128 + tid] = g + bY;
        } else if (tid >= 128) {
            float g = dot64(wX, sh_ho);
            sh_gh[tid - 128] = g + bX;
        }
        __syncthreads();

        // ---- P4: gates + h update + output store + prefetch commit ----
        if (tid < 64) {
            int j = tid;
            float r = sigmoidf_(sh_gx[j]       + sh_gh[j]);
            float z = sigmoidf_(sh_gx[64 + j]  + sh_gh[64 + j]);
            float n = tanhf(sh_gx[128 + j] + r * sh_gh[128 + j]);
            float ho = sh_ho[j];
            float hn = (1.f - z) * n + z * ho;
            sh_h[j] = hn;
            outb[(size_t)t * ND + j] = hn;
            if (t == sl - 1) fin = hn;
            sh_x[nxt][j] = (tn < sl) ? xr : 0.f;   // PaddedBatch mask on x
        }
        if (tid == 64) sh_dt[nxt] = (tn < sl) ? dtr : 0.f;  // mask on dt
        __syncthreads();
    }

    // final hidden state: outputs[b, sl-1, :] -> second output tensor (1,B,D)
    if (tid < 64)
        out[(size_t)NB * NL * ND + (size_t)b * ND + tid] = fin;
}

extern "C" void kernel_launch(void* const* d_in, const int* in_sizes, int n_in,
                              void* d_out, int out_size)
{
    const float* x    = (const float*)d_in[0];
    const float* tdel = (const float*)d_in[1];
    const int*   seq  = (const int*)  d_in[2];
    const float* h0   = (const float*)d_in[3];
    const float* w_ih = (const float*)d_in[4];
    const float* w_hh = (const float*)d_in[5];
    const float* b_ih = (const float*)d_in[6];
    const float* b_hh = (const float*)d_in[7];
    const float* dw1  = (const float*)d_in[8];
    const float* db1  = (const float*)d_in[9];
    const float* dw2  = (const float*)d_in[10];
    const float* db2  = (const float*)d_in[11];

    odegru_kernel<<<NB, 256>>>(x, tdel, seq, h0, w_ih, w_hh, b_ih, b_hh,
                               dw1, db1, dw2, db2, (float*)d_out);
}

// round 5
// speedup vs baseline: 1.1447x; 1.1447x over previous
#include <cuda_runtime.h>
#include <cuda_bf16.h>

// ODE-GRU: B=128 sequences, L=2048 steps, I=D=64.
// One CTA per batch element, 256 threads. Weights register-resident
// (2 rows/thread, stored packed as f32x2 in u64). All GEMV work done with
// fma.rn.f32x2 (packed FFMA2, PTX-only) to halve FMA-pipe issue count.

#define NB 128
#define NL 2048
#define NI 64
#define ND 64
#define NG 192  // 3*D

typedef unsigned long long u64;

__device__ __forceinline__ u64 fma2(u64 a, u64 b, u64 c) {
    u64 d;
    asm("fma.rn.f32x2 %0, %1, %2, %3;" : "=l"(d) : "l"(a), "l"(b), "l"(c));
    return d;
}
__device__ __forceinline__ u64 add2(u64 a, u64 b) {
    u64 d;
    asm("add.rn.f32x2 %0, %1, %2;" : "=l"(d) : "l"(a), "l"(b));
    return d;
}
__device__ __forceinline__ u64 pk(float lo, float hi) {
    u64 r;
    asm("mov.b64 %0, {%1, %2};" : "=l"(r) : "f"(lo), "f"(hi));
    return r;
}

// dot(w_row, v) + bias, with w pre-packed (w[k] = {row[2k], row[2k+1]}).
__device__ __forceinline__ float dot64p(const u64* __restrict__ w,
                                        const float* __restrict__ v,
                                        float bias)
{
    const ulonglong2* __restrict__ v2 = (const ulonglong2*)v;
    u64 a0 = pk(bias, 0.f), a1 = 0ull, a2 = 0ull, a3 = 0ull;
#pragma unroll
    for (int q = 0; q < 8; q++) {
        ulonglong2 p = v2[2*q];      // elements 8q+0..3
        ulonglong2 r = v2[2*q + 1];  // elements 8q+4..7
        a0 = fma2(w[4*q+0], p.x, a0);
        a1 = fma2(w[4*q+1], p.y, a1);
        a2 = fma2(w[4*q+2], r.x, a2);
        a3 = fma2(w[4*q+3], r.y, a3);
    }
    u64 s = add2(add2(a0, a1), add2(a2, a3));
    float lo = __uint_as_float((unsigned)s);
    float hi = __uint_as_float((unsigned)(s >> 32));
    return lo + hi;
}

__device__ __forceinline__ float sigmoidf_(float a) {
    return __fdividef(1.f, 1.f + __expf(-a));
}
__device__ __forceinline__ float tanhf_fast(float x) {
    // 1 - 2/(exp(2x)+1): abs err ~1e-7, saturates to +/-1 correctly
    float e = __expf(2.f * x);
    return 1.f - __fdividef(2.f, e + 1.f);
}

__global__ __launch_bounds__(256, 1)
void odegru_kernel(const float* __restrict__ x,
                   const float* __restrict__ tdel,
                   const int*   __restrict__ seq,
                   const float* __restrict__ h0,
                   const float* __restrict__ w_ih,
                   const float* __restrict__ w_hh,
                   const float* __restrict__ b_ih,
                   const float* __restrict__ b_hh,
                   const float* __restrict__ dw1,
                   const float* __restrict__ db1,
                   const float* __restrict__ dw2,
                   const float* __restrict__ db2,
                   float* __restrict__ out)
{
    const int b   = blockIdx.x;
    const int tid = threadIdx.x;

    __shared__ __align__(16) float sh_h[ND];
    __shared__ __align__(16) float sh_t1[ND];
    __shared__ __align__(16) float sh_ho[ND];
    __shared__ __align__(16) float sh_gx[NG];
    __shared__ __align__(16) float sh_gh[128];   // rows 0..127 only (128+j kept in reg)
    __shared__ __align__(16) float sh_x[2][NI];
    __shared__ float sh_dt[2];

    // ---- per-thread packed weight rows ----
    // thr   0- 63: wX = dw1 row j        (P1)   wY = w_hh row 128+j (P3)
    // thr  64-127: wX = dw2 row j        (P2)   wY = w_ih row j     (P1)
    // thr 128-255: wX = w_hh row tid-128 (P3)   wY = w_ih row tid-64(P1)
    u64 wX[32], wY[32];
    float bX, bY;
    const float* pX;
    const float* pY;
    if (tid < 64) {
        pX = dw1 + tid * 64;          bX = db1[tid];
        pY = w_hh + (128 + tid) * 64; bY = b_hh[128 + tid];
    } else if (tid < 128) {
        int j = tid - 64;
        pX = dw2 + j * 64;            bX = db2[j];
        pY = w_ih + j * 64;           bY = b_ih[j];
    } else {
        pX = w_hh + (tid - 128) * 64; bX = b_hh[tid - 128];
        pY = w_ih + (tid - 64) * 64;  bY = b_ih[tid - 64];
    }
#pragma unroll
    for (int k = 0; k < 32; k++) {
        // rows are 256B-aligned slices of aligned tensors; 8B loads are legal
        wX[k] = ((const u64*)pX)[k];
        wY[k] = ((const u64*)pY)[k];
    }

    const int sl = seq[b];
    const float* xb = x + (size_t)b * NL * NI;
    float* outb     = out + (size_t)b * NL * ND;

    if (tid < 64) {
        sh_h[tid]    = h0[tid];
        sh_x[0][tid] = xb[tid];              // t=0 always live (sl >= 1)
    }
    if (tid == 64) sh_dt[0] = tdel[(size_t)b * NL];

    // 2-deep x/dt prefetch: xA holds data for step t+1
    float xA = 0.f, dtA = 0.f;
    if (tid < 64)  xA  = xb[NI + tid];
    if (tid == 64) dtA = tdel[(size_t)b * NL + 1];

    float fin = 0.f;
    __syncthreads();

    for (int t = 0; t < NL; t++) {
        const int cur = t & 1, nxt = cur ^ 1;
        const int tn  = t + 1;

        // prefetch for step t+2 (consumed two iterations out)
        float xB = 0.f, dtB = 0.f;
        if (t + 2 < NL) {
            if (tid < 64)   xB  = xb[(size_t)(t + 2) * NI + tid];
            if (tid == 64)  dtB = tdel[(size_t)b * NL + t + 2];
        }

        // ---- P1: u = tanh(h*dw1^T + db1)  ||  gx = x_t*w_ih^T + b_ih ----
        if (tid < 64) {
            float u = dot64p(wX, sh_h, bX);
            sh_t1[tid] = tanhf_fast(u);
        } else {
            sh_gx[tid - 64] = dot64p(wY, sh_x[cur], bY);
        }
        __syncthreads();

        // ---- P2: d = u*dw2^T + db2;  h_ode = h + d*dt ----
        if (tid >= 64 && tid < 128) {
            int j = tid - 64;
            float d = dot64p(wX, sh_t1, bX);
            sh_ho[j] = fmaf(d, sh_dt[cur], sh_h[j]);
        }
        __syncthreads();

        // ---- P3: gh = h_ode*w_hh^T + b_hh ----
        float gn = 0.f;                      // gh[128+j], kept local by thread j
        if (tid < 64) {
            gn = dot64p(wY, sh_ho, bY);
        } else if (tid >= 128) {
            sh_gh[tid - 128] = dot64p(wX, sh_ho, bX);
        }
        __syncthreads();

        // ---- P4: gates + h update + output store + prefetch commit ----
        if (tid < 64) {
            int j = tid;
            float r  = sigmoidf_(sh_gx[j]      + sh_gh[j]);
            float z  = sigmoidf_(sh_gx[64 + j] + sh_gh[64 + j]);
            float n  = tanhf_fast(fmaf(r, gn, sh_gx[128 + j]));
            float ho = sh_ho[j];
            float hn = fmaf(z, ho - n, n);   // (1-z)*n + z*ho
            sh_h[j] = hn;
            outb[(size_t)t * ND + j] = hn;
            if (t == sl - 1) fin = hn;
            sh_x[nxt][j] = (tn < sl) ? xA : 0.f;   // PaddedBatch mask on x
        }
        if (tid == 64) sh_dt[nxt] = (tn < sl) ? dtA : 0.f;
        xA = xB; dtA = dtB;
        __syncthreads();
    }

    // final hidden state -> second output tensor (1, B, D)
    if (tid < 64)
        out[(size_t)NB * NL * ND + (size_t)b * ND + tid] = fin;
}

extern "C" void kernel_launch(void* const* d_in, const int* in_sizes, int n_in,
                              void* d_out, int out_size)
{
    const float* x    = (const float*)d_in[0];
    const float* tdel = (const float*)d_in[1];
    const int*   seq  = (const int*)  d_in[2];
    const float* h0   = (const float*)d_in[3];
    const float* w_ih = (const float*)d_in[4];
    const float* w_hh = (const float*)d_in[5];
    const float* b_ih = (const float*)d_in[6];
    const float* b_hh = (const float*)d_in[7];
    const float* dw1  = (const float*)d_in[8];
    const float* db1  = (const float*)d_in[9];
    const float* dw2  = (const float*)d_in[10];
    const float* db2  = (const float*)d_in[11];

    odegru_kernel<<<NB, 256>>>(x, tdel, seq, h0, w_ih, w_hh, b_ih, b_hh,
                               dw1, db1, dw2, db2, (float*)d_out);
}